// round 14
// baseline (speedup 1.0000x reference)
#include <cuda_runtime.h>
#include <cuda_bf16.h>
#include <cuda_fp16.h>

// Problem constants
#define BATCH 256
#define SEQ   196
#define CH    768
#define NH    12
#define HD    64
#define M_ROWS (BATCH * SEQ)       // 50176
#define THREE_C (3 * CH)           // 2304
#define SCALE 0.125f
#define RPB_LD 208                 // padded rpb row length (halves)

// Scratch (q/k/v half, [B,H,N,hd])
__device__ __half g_q[(size_t)BATCH * NH * SEQ * HD];
__device__ __half g_k[(size_t)BATCH * NH * SEQ * HD];
__device__ __half g_v[(size_t)BATCH * NH * SEQ * HD];
__device__ __half g_rpbh[(size_t)NH * SEQ * RPB_LD];   // [H,196,208] half
__device__ __half g_att[(size_t)M_ROWS * CH];          // [B,N,C] half
__device__ __half g_xh[(size_t)M_ROWS * CH];
__device__ __half g_wh[(size_t)THREE_C * CH];
__device__ __half g_pwh[(size_t)CH * CH];

// ---------------------------------------------------------------------------
// PTX helpers
// ---------------------------------------------------------------------------
__device__ __forceinline__ void cp_async16(void* smem_ptr, const void* gmem_ptr) {
    unsigned saddr = (unsigned)__cvta_generic_to_shared(smem_ptr);
    asm volatile("cp.async.cg.shared.global [%0], [%1], 16;\n"
                 :: "r"(saddr), "l"(gmem_ptr));
}
__device__ __forceinline__ void cp_commit() {
    asm volatile("cp.async.commit_group;\n");
}
template <int N>
__device__ __forceinline__ void cp_wait() {
    asm volatile("cp.async.wait_group %0;\n" :: "n"(N));
}
__device__ __forceinline__ void mma_f16(float c[4], unsigned a0, unsigned a1,
                                        unsigned a2, unsigned a3,
                                        unsigned b0, unsigned b1) {
    asm volatile(
        "mma.sync.aligned.m16n8k16.row.col.f32.f16.f16.f32 "
        "{%0,%1,%2,%3}, {%4,%5,%6,%7}, {%8,%9}, {%0,%1,%2,%3};\n"
        : "+f"(c[0]), "+f"(c[1]), "+f"(c[2]), "+f"(c[3])
        : "r"(a0), "r"(a1), "r"(a2), "r"(a3), "r"(b0), "r"(b1));
}
__device__ __forceinline__ void ldm_x4(unsigned& r0, unsigned& r1,
                                       unsigned& r2, unsigned& r3, unsigned addr) {
    asm volatile("ldmatrix.sync.aligned.m8n8.x4.shared.b16 {%0,%1,%2,%3}, [%4];"
                 : "=r"(r0), "=r"(r1), "=r"(r2), "=r"(r3) : "r"(addr));
}

// ---------------------------------------------------------------------------
// Kernel 0: fp32 -> half conversion
// ---------------------------------------------------------------------------
__global__ void to_half_kernel(const float* __restrict__ src,
                               __half* __restrict__ dst, int n4)
{
    int i = blockIdx.x * blockDim.x + threadIdx.x;
    if (i >= n4) return;
    float4 v = ((const float4*)src)[i];
    ((__half2*)dst)[i * 2 + 0] = __floats2half2_rn(v.x, v.y);
    ((__half2*)dst)[i * 2 + 1] = __floats2half2_rn(v.z, v.w);
}

// ---------------------------------------------------------------------------
// FP16 mma GEMM, ldmatrix fragments, BK=64, 3-stage pipeline.
// Block 128x256x64h, 512 threads (16 warps = 2m x 8n), warp tile 64x32.
// ---------------------------------------------------------------------------
#define BM 128
#define BN 256
#define BK 64
#define NSTAGE 3
#define LDH 72
#define NTHREADS 512
#define STAGE_HALVES ((BM + BN) * LDH)                  // 27648
#define STAGE_BYTES (STAGE_HALVES * 2)                  // 55296
#define GEMM_SMEM_BYTES (NSTAGE * STAGE_BYTES)          // 165888
#define CLD 264                    // qkv C bounce row stride (halves)

__device__ __forceinline__
void gemm_mainloop(const __half* __restrict__ Aptr,
                   const __half* __restrict__ Bptr,
                   __half* smh, int tid, float acc[4][4][4])
{
    const int warp = tid >> 5;
    const int lane = tid & 31;
    const int wr = warp & 1;       // 64-row slab
    const int wc = warp >> 1;      // 0..7, 32-col slab
    const int grp = lane >> 3;
    const int lrow = lane & 7;

    #pragma unroll
    for (int i = 0; i < 4; i++)
        #pragma unroll
        for (int j = 0; j < 4; j++)
            #pragma unroll
            for (int t = 0; t < 4; t++) acc[i][j][t] = 0.f;

    auto prefetch = [&](int stage, int k0) {
        __half* As = smh + stage * STAGE_HALVES;
        __half* Bs = As + BM * LDH;
        #pragma unroll
        for (int i = 0; i < 2; i++) {          // A: 128 rows x 8 chunks
            const int idx = tid + i * NTHREADS;
            const int row = idx >> 3, ch = idx & 7;
            cp_async16(As + row * LDH + ch * 8,
                       Aptr + (size_t)row * CH + k0 + ch * 8);
        }
        #pragma unroll
        for (int i = 0; i < 4; i++) {          // B: 256 rows x 8 chunks
            const int idx = tid + i * NTHREADS;
            const int row = idx >> 3, ch = idx & 7;
            cp_async16(Bs + row * LDH + ch * 8,
                       Bptr + (size_t)row * CH + k0 + ch * 8);
        }
    };

    prefetch(0, 0);   cp_commit();
    prefetch(1, BK);  cp_commit();

    const unsigned smbase = (unsigned)__cvta_generic_to_shared(smh);
    const unsigned a_off = ((wr * 64 + (grp & 1) * 8 + lrow) * LDH
                            + (grp >> 1) * 8) * 2;
    const unsigned b_off = (unsigned)(BM * LDH * 2)
                         + ((wc * 32 + (grp >> 1) * 8 + lrow) * LDH
                            + (grp & 1) * 8) * 2;

    const int NKT = CH / BK;     // 12
    int sC = 0, sF = 2;

    #pragma unroll 1
    for (int kt = 0; kt < NKT; kt++) {
        cp_wait<1>();
        __syncthreads();

        if (kt + 2 < NKT) prefetch(sF, (kt + 2) * BK);
        cp_commit();

        const unsigned stage_addr = smbase + sC * STAGE_BYTES;
        const unsigned a_base = stage_addr + a_off;
        const unsigned b_base = stage_addr + b_off;

        #pragma unroll
        for (int s = 0; s < 4; s++) {
            unsigned a[4][4], b[4][2];
            #pragma unroll
            for (int mi = 0; mi < 4; mi++)
                ldm_x4(a[mi][0], a[mi][1], a[mi][2], a[mi][3],
                       a_base + (mi * 16 * LDH + s * 16) * 2);
            #pragma unroll
            for (int np = 0; np < 2; np++)
                ldm_x4(b[2 * np][0], b[2 * np][1], b[2 * np + 1][0], b[2 * np + 1][1],
                       b_base + (np * 16 * LDH + s * 16) * 2);
            #pragma unroll
            for (int mi = 0; mi < 4; mi++)
                #pragma unroll
                for (int ni = 0; ni < 4; ni++)
                    mma_f16(acc[mi][ni], a[mi][0], a[mi][1], a[mi][2], a[mi][3],
                            b[ni][0], b[ni][1]);
        }
        sC = (sC + 1 == NSTAGE) ? 0 : sC + 1;
        sF = (sF + 1 == NSTAGE) ? 0 : sF + 1;
    }
}

// ---------------------------------------------------------------------------
// Kernel 1: fused QKV projection -> half q/k/v (smem-bounced coalesced stores)
// ---------------------------------------------------------------------------
__global__ __launch_bounds__(NTHREADS, 1)
void qkv_gemm_kernel(const float* __restrict__ qb,
                     const float* __restrict__ vb)
{
    extern __shared__ __half smh[];
    const int bn = blockIdx.x;     // 0..8 (THREE_C/256)
    const int bm = blockIdx.y;     // 0..391
    const int tid = threadIdx.x;

    float acc[4][4][4];
    gemm_mainloop(g_xh + (size_t)(bm * BM) * CH, g_wh + (size_t)(bn * BN) * CH,
                  smh, tid, acc);

    const int warp = tid >> 5;
    const int lane = tid & 31;
    const int g = lane >> 2, tg = lane & 3;
    const int wr = warp & 1, wc = warp >> 1;

    const int jblock = bn * BN;
    const int which = jblock / CH;   // uniform: 768 = 3*256

    __syncthreads();   // ldmatrix reads done before overwriting stage smem

    // bias+scale into smem bounce tile [128][CLD] half
    #pragma unroll
    for (int mi = 0; mi < 4; mi++) {
        #pragma unroll
        for (int ni = 0; ni < 4; ni++) {
            const int jl = wc * 32 + ni * 8 + tg * 2;
            const int cbase = jblock + jl - which * CH;
            #pragma unroll
            for (int rr = 0; rr < 2; rr++) {
                const int row = wr * 64 + mi * 16 + g + rr * 8;
                const float v0 = acc[mi][ni][rr * 2 + 0];
                const float v1 = acc[mi][ni][rr * 2 + 1];
                __half2 h2;
                if (which == 0) {
                    float2 qb2 = *(const float2*)(qb + cbase);
                    h2 = __floats2half2_rn((v0 + qb2.x) * SCALE, (v1 + qb2.y) * SCALE);
                } else if (which == 1) {
                    h2 = __floats2half2_rn(v0, v1);
                } else {
                    float2 vb2 = *(const float2*)(vb + cbase);
                    h2 = __floats2half2_rn(v0 + vb2.x, v1 + vb2.y);
                }
                *(__half2*)(smh + row * CLD + jl) = h2;
            }
        }
    }
    __syncthreads();

    // coalesced write-out: 16B chunks (128 rows x 32 chunks = 4096)
    __half* dstT = (which == 0) ? g_q : (which == 1) ? g_k : g_v;
    #pragma unroll
    for (int it = 0; it < 8; it++) {
        const int idx = tid + it * NTHREADS;    // 0..4095
        const int r = idx >> 5;                 // row 0..127
        const int cb = (idx & 31) * 8;          // col base 0..248
        const int cbase = jblock + cb - which * CH;
        const int h = cbase >> 6;
        const int d = cbase & 63;
        const int m = bm * BM + r;
        const int b = m / SEQ;
        const int n = m - b * SEQ;
        const uint4 val = *(const uint4*)(smh + r * CLD + cb);
        *(uint4*)(dstT + (((size_t)(b * NH + h)) * SEQ + n) * HD + d) = val;
    }
}

// ---------------------------------------------------------------------------
// Kernel 2: rpb gather -> half, padded [H][196][208]
// ---------------------------------------------------------------------------
__global__ void rpb_gather_kernel(const float* __restrict__ table,
                                  const int* __restrict__ relidx)
{
    int idx = blockIdx.x * blockDim.x + threadIdx.x;
    const int total = NH * SEQ * RPB_LD;
    if (idx >= total) return;
    const int h = idx / (SEQ * RPB_LD);
    const int rem = idx - h * SEQ * RPB_LD;
    const int i = rem / RPB_LD;
    const int j = rem - i * RPB_LD;
    __half v = __float2half(0.f);
    if (j < SEQ) v = __float2half(table[relidx[i * SEQ + j] * NH + h]);
    g_rpbh[idx] = v;
}

// ---------------------------------------------------------------------------
// Kernel 3: FP16 mma attention; rpb staged in smem via cp.async.
// ---------------------------------------------------------------------------
#define LQ 72
#define LV 216
#define LP 216
#define RB_LD 216
#define KOFFH (128 * LP)                  // 27648
#define VOFFH (KOFFH + 200 * LQ)          // 42048
#define RBOFFH (VOFFH + 64 * LV)          // 55872
#define AT_SMEM_BYTES ((RBOFFH + 128 * RB_LD) * 2)   // 167040 bytes

__global__ __launch_bounds__(256, 1)
void attn_mma_kernel()
{
    extern __shared__ __half smh[];
    __half* P  = smh;                // [128][LP]
    __half* Qs = smh;                // [128][LQ] overlay
    __half* Ks = smh + KOFFH;        // [200][LQ]
    __half* Vt = smh + VOFFH;        // [64][LV] transposed V
    __half* RB = smh + RBOFFH;       // [128][RB_LD] rpb tile

    const int bh = blockIdx.x;
    const int b = bh / NH;
    const int h = bh % NH;
    const int tid = threadIdx.x;
    const int warp = tid >> 5;
    const int lane = tid & 31;
    const int g = lane >> 2;
    const int tg = lane & 3;

    const __half* Qg = g_q + (size_t)bh * SEQ * HD;
    const __half* Kg = g_k + (size_t)bh * SEQ * HD;
    const __half* Vg = g_v + (size_t)bh * SEQ * HD;
    const __half* rpbh = g_rpbh + (size_t)h * SEQ * RPB_LD;

    const uint4 z16 = make_uint4(0, 0, 0, 0);

    for (int t = tid; t < 200 * 8; t += 256) {
        const int r = t >> 3, c = (t & 7) * 8;
        if (r < SEQ) cp_async16(Ks + r * LQ + c, Kg + r * HD + c);
        else         *(uint4*)(Ks + r * LQ + c) = z16;
    }
    for (int t = tid; t < SEQ * 8; t += 256) {
        const int key = t >> 3, d0 = (t & 7) * 8;
        const uint4 raw = *(const uint4*)(Vg + key * HD + d0);
        const __half* hp = (const __half*)&raw;
        #pragma unroll
        for (int j = 0; j < 8; j++)
            Vt[(d0 + j) * LV + key] = hp[j];
    }
    for (int t = tid; t < 64 * 20; t += 256) {
        const int d = t / 20, kk = SEQ + t % 20;
        Vt[d * LV + kk] = __ushort_as_half((unsigned short)0);
    }
    cp_commit();

    __half* attbase = g_att + (size_t)b * SEQ * CH + h * HD;

    #pragma unroll 1
    for (int mt = 0; mt < 2; mt++) {
        const int qbase = mt * 128;
        const int qrows = mt ? (SEQ - 128) : 128;

        __syncthreads();
        for (int t = tid; t < 128 * 8; t += 256) {
            const int r = t >> 3, c = (t & 7) * 8;
            if (r < qrows)
                cp_async16(Qs + r * LQ + c, Qg + (qbase + r) * HD + c);
            else
                *(uint4*)(Qs + r * LQ + c) = z16;
        }
        for (int t = tid; t < 128 * 26; t += 256) {
            const int r = t / 26, ch = (t % 26) * 8;
            if (r < qrows)
                cp_async16(RB + r * RB_LD + ch,
                           rpbh + (size_t)(qbase + r) * RPB_LD + ch);
            else
                *(uint4*)(RB + r * RB_LD + ch) = z16;
        }
        cp_commit();
        cp_wait<0>();
        __syncthreads();

        const int r0 = warp * 16;
        float acc[25][4];
        #pragma unroll
        for (int t = 0; t < 25; t++)
            #pragma unroll
            for (int e = 0; e < 4; e++) acc[t][e] = 0.f;

        #pragma unroll
        for (int ks = 0; ks < 4; ks++) {
            const int k0 = ks * 16;
            const __half* qa = Qs + (r0 + g) * LQ + k0 + 2 * tg;
            const unsigned a0 = *(const unsigned*)(qa);
            const unsigned a1 = *(const unsigned*)(qa + 8 * LQ);
            const unsigned a2 = *(const unsigned*)(qa + 8);
            const unsigned a3 = *(const unsigned*)(qa + 8 * LQ + 8);
            #pragma unroll
            for (int t = 0; t < 25; t++) {
                const __half* kb = Ks + (t * 8 + g) * LQ + k0 + 2 * tg;
                const unsigned b0 = *(const unsigned*)(kb);
                const unsigned b1 = *(const unsigned*)(kb + 8);
                mma_f16(acc[t], a0, a1, a2, a3, b0, b1);
            }
        }
        __syncthreads();

        const int rlo = qbase + r0 + g;
        const int rhi = rlo + 8;
        const __half* RBlo = RB + (r0 + g) * RB_LD;
        const __half* RBhi = RB + (r0 + g + 8) * RB_LD;
        #pragma unroll
        for (int t = 0; t < 25; t++) {
            const int c0 = t * 8 + 2 * tg;
            const float2 flo = __half22float2(*(const __half2*)(RBlo + c0));
            const float2 fhi = __half22float2(*(const __half2*)(RBhi + c0));
            if (c0 < SEQ)     { acc[t][0] += flo.x; acc[t][2] += fhi.x; }
            else              { acc[t][0] = -1e30f; acc[t][2] = -1e30f; }
            if (c0 + 1 < SEQ) { acc[t][1] += flo.y; acc[t][3] += fhi.y; }
            else              { acc[t][1] = -1e30f; acc[t][3] = -1e30f; }
        }

        float mlo = -1e30f, mhi = -1e30f;
        #pragma unroll
        for (int t = 0; t < 25; t++) {
            mlo = fmaxf(mlo, fmaxf(acc[t][0], acc[t][1]));
            mhi = fmaxf(mhi, fmaxf(acc[t][2], acc[t][3]));
        }
        mlo = fmaxf(mlo, __shfl_xor_sync(0xffffffffu, mlo, 1));
        mlo = fmaxf(mlo, __shfl_xor_sync(0xffffffffu, mlo, 2));
        mhi = fmaxf(mhi, __shfl_xor_sync(0xffffffffu, mhi, 1));
        mhi = fmaxf(mhi, __shfl_xor_sync(0xffffffffu, mhi, 2));

        float llo = 0.f, lhi = 0.f;
        __half* Prow_lo = P + (r0 + g) * LP;
        __half* Prow_hi = P + (r0 + g + 8) * LP;
        #pragma unroll
        for (int t = 0; t < 25; t++) {
            const int c0 = t * 8 + 2 * tg;
            const __half2 p01 = __floats2half2_rn(__expf(acc[t][0] - mlo),
                                                  __expf(acc[t][1] - mlo));
            const __half2 p23 = __floats2half2_rn(__expf(acc[t][2] - mhi),
                                                  __expf(acc[t][3] - mhi));
            const float2 f01 = __half22float2(p01);
            const float2 f23 = __half22float2(p23);
            llo += f01.x + f01.y;
            lhi += f23.x + f23.y;
            *(__half2*)(Prow_lo + c0) = p01;
            *(__half2*)(Prow_hi + c0) = p23;
        }
        *(__half2*)(Prow_lo + 200 + 2 * tg) = __floats2half2_rn(0.f, 0.f);
        *(__half2*)(Prow_hi + 200 + 2 * tg) = __floats2half2_rn(0.f, 0.f);

        llo += __shfl_xor_sync(0xffffffffu, llo, 1);
        llo += __shfl_xor_sync(0xffffffffu, llo, 2);
        lhi += __shfl_xor_sync(0xffffffffu, lhi, 1);
        lhi += __shfl_xor_sync(0xffffffffu, lhi, 2);
        const float inv_lo = 1.f / llo;
        const float inv_hi = 1.f / lhi;

        __syncwarp();

        float oacc[8][4];
        #pragma unroll
        for (int nt = 0; nt < 8; nt++)
            #pragma unroll
            for (int e = 0; e < 4; e++) oacc[nt][e] = 0.f;

        #pragma unroll
        for (int kt = 0; kt < 13; kt++) {
            const int k0 = kt * 16;
            const __half* pa = P + (r0 + g) * LP + k0 + 2 * tg;
            const unsigned a0 = *(const unsigned*)(pa);
            const unsigned a1 = *(const unsigned*)(pa + 8 * LP);
            const unsigned a2 = *(const unsigned*)(pa + 8);
            const unsigned a3 = *(const unsigned*)(pa + 8 * LP + 8);
            #pragma unroll
            for (int nt = 0; nt < 8; nt++) {
                const __half* vb = Vt + (nt * 8 + g) * LV + k0 + 2 * tg;
                const unsigned b0 = *(const unsigned*)(vb);
                const unsigned b1 = *(const unsigned*)(vb + 8);
                mma_f16(oacc[nt], a0, a1, a2, a3, b0, b1);
            }
        }

        #pragma unroll
        for (int nt = 0; nt < 8; nt++) {
            const int c = nt * 8 + 2 * tg;
            if (rlo < SEQ)
                *(__half2*)(attbase + (size_t)rlo * CH + c) =
                    __floats2half2_rn(oacc[nt][0] * inv_lo, oacc[nt][1] * inv_lo);
            if (rhi < SEQ)
                *(__half2*)(attbase + (size_t)rhi * CH + c) =
                    __floats2half2_rn(oacc[nt][2] * inv_hi, oacc[nt][3] * inv_hi);
        }
    }
}

// ---------------------------------------------------------------------------
// Kernel 4: output projection
// ---------------------------------------------------------------------------
__global__ __launch_bounds__(NTHREADS, 1)
void proj_gemm_kernel(const float* __restrict__ pb,
                      float* __restrict__ out)
{
    extern __shared__ __half smh[];
    const int bn = blockIdx.x;    // 0..2 (CH/256)
    const int bm = blockIdx.y;
    const int tid = threadIdx.x;

    float acc[4][4][4];
    gemm_mainloop(g_att + (size_t)(bm * BM) * CH, g_pwh + (size_t)(bn * BN) * CH,
                  smh, tid, acc);

    const int warp = tid >> 5;
    const int lane = tid & 31;
    const int g = lane >> 2, tg = lane & 3;
    const int wr = warp & 1, wc = warp >> 1;

    #pragma unroll
    for (int mi = 0; mi < 4; mi++) {
        #pragma unroll
        for (int ni = 0; ni < 4; ni++) {
            const int j = bn * BN + wc * 32 + ni * 8 + tg * 2;
            const float2 pb2 = *(const float2*)(pb + j);
            #pragma unroll
            for (int rr = 0; rr < 2; rr++) {
                const int i = bm * BM + wr * 64 + mi * 16 + g + rr * 8;
                float2 o2;
                o2.x = acc[mi][ni][rr * 2 + 0] + pb2.x;
                o2.y = acc[mi][ni][rr * 2 + 1] + pb2.y;
                *(float2*)(out + (size_t)i * CH + j) = o2;
            }
        }
    }
}

// ---------------------------------------------------------------------------
// Launch
// ---------------------------------------------------------------------------
extern "C" void kernel_launch(void* const* d_in, const int* in_sizes, int n_in,
                              void* d_out, int out_size)
{
    const float* x       = (const float*)d_in[0];
    const float* qkv_w   = (const float*)d_in[1];
    const float* q_bias  = (const float*)d_in[2];
    const float* v_bias  = (const float*)d_in[3];
    const float* rpb_tab = (const float*)d_in[4];
    const float* proj_w  = (const float*)d_in[5];
    const float* proj_b  = (const float*)d_in[6];
    const int*   relidx  = (const int*)d_in[7];
    float*       out     = (float*)d_out;

    static bool attrs_set = false;
    if (!attrs_set) {
        cudaFuncSetAttribute(qkv_gemm_kernel,
                             cudaFuncAttributeMaxDynamicSharedMemorySize,
                             GEMM_SMEM_BYTES);
        cudaFuncSetAttribute(proj_gemm_kernel,
                             cudaFuncAttributeMaxDynamicSharedMemorySize,
                             GEMM_SMEM_BYTES);
        cudaFuncSetAttribute(attn_mma_kernel,
                             cudaFuncAttributeMaxDynamicSharedMemorySize,
                             AT_SMEM_BYTES);
        attrs_set = true;
    }

    __half* xh_p;  cudaGetSymbolAddress((void**)&xh_p,  g_xh);
    __half* wh_p;  cudaGetSymbolAddress((void**)&wh_p,  g_wh);
    __half* pwh_p; cudaGetSymbolAddress((void**)&pwh_p, g_pwh);

    // 0. Convert GEMM operands to half
    {
        int n4 = (M_ROWS * CH) / 4;
        to_half_kernel<<<(n4 + 255) / 256, 256>>>(x, xh_p, n4);
        n4 = (THREE_C * CH) / 4;
        to_half_kernel<<<(n4 + 255) / 256, 256>>>(qkv_w, wh_p, n4);
        n4 = (CH * CH) / 4;
        to_half_kernel<<<(n4 + 255) / 256, 256>>>(proj_w, pwh_p, n4);
    }
    // 1. QKV projection (BN=256, 512 threads)
    {
        dim3 grid(THREE_C / BN, M_ROWS / BM);   // (9, 392)
        qkv_gemm_kernel<<<grid, NTHREADS, GEMM_SMEM_BYTES>>>(q_bias, v_bias);
    }
    // 2. RPB gather (half, padded)
    {
        const int total = NH * SEQ * RPB_LD;
        rpb_gather_kernel<<<(total + 255) / 256, 256>>>(rpb_tab, relidx);
    }
    // 3. Attention (fp16 mma, rpb staged in smem)
    {
        attn_mma_kernel<<<BATCH * NH, 256, AT_SMEM_BYTES>>>();
    }
    // 4. Projection (BN=256, 512 threads)
    {
        dim3 grid(CH / BN, M_ROWS / BM);        // (3, 392)
        proj_gemm_kernel<<<grid, NTHREADS, GEMM_SMEM_BYTES>>>(proj_b, out);
    }
}

// round 15
// speedup vs baseline: 1.0246x; 1.0246x over previous
#include <cuda_runtime.h>
#include <cuda_bf16.h>
#include <cuda_fp16.h>

// Problem constants
#define BATCH 256
#define SEQ   196
#define CH    768
#define NH    12
#define HD    64
#define M_ROWS (BATCH * SEQ)       // 50176
#define THREE_C (3 * CH)           // 2304
#define SCALE 0.125f
#define RPB_LD 208                 // padded rpb row length (halves)

// Scratch (q/k/v half, [B,H,N,hd])
__device__ __half g_q[(size_t)BATCH * NH * SEQ * HD];
__device__ __half g_k[(size_t)BATCH * NH * SEQ * HD];
__device__ __half g_v[(size_t)BATCH * NH * SEQ * HD];
__device__ __half g_rpbh[(size_t)NH * SEQ * RPB_LD];   // [H,196,208] half
__device__ __half g_att[(size_t)M_ROWS * CH];          // [B,N,C] half
__device__ __half g_xh[(size_t)M_ROWS * CH];
__device__ __half g_wh[(size_t)THREE_C * CH];
__device__ __half g_pwh[(size_t)CH * CH];

// ---------------------------------------------------------------------------
// PTX helpers
// ---------------------------------------------------------------------------
__device__ __forceinline__ void cp_async16(void* smem_ptr, const void* gmem_ptr) {
    unsigned saddr = (unsigned)__cvta_generic_to_shared(smem_ptr);
    asm volatile("cp.async.cg.shared.global [%0], [%1], 16;\n"
                 :: "r"(saddr), "l"(gmem_ptr));
}
__device__ __forceinline__ void cp_commit() {
    asm volatile("cp.async.commit_group;\n");
}
template <int N>
__device__ __forceinline__ void cp_wait() {
    asm volatile("cp.async.wait_group %0;\n" :: "n"(N));
}
__device__ __forceinline__ void mma_f16(float c[4], unsigned a0, unsigned a1,
                                        unsigned a2, unsigned a3,
                                        unsigned b0, unsigned b1) {
    asm volatile(
        "mma.sync.aligned.m16n8k16.row.col.f32.f16.f16.f32 "
        "{%0,%1,%2,%3}, {%4,%5,%6,%7}, {%8,%9}, {%0,%1,%2,%3};\n"
        : "+f"(c[0]), "+f"(c[1]), "+f"(c[2]), "+f"(c[3])
        : "r"(a0), "r"(a1), "r"(a2), "r"(a3), "r"(b0), "r"(b1));
}
__device__ __forceinline__ void ldm_x4(unsigned& r0, unsigned& r1,
                                       unsigned& r2, unsigned& r3, unsigned addr) {
    asm volatile("ldmatrix.sync.aligned.m8n8.x4.shared.b16 {%0,%1,%2,%3}, [%4];"
                 : "=r"(r0), "=r"(r1), "=r"(r2), "=r"(r3) : "r"(addr));
}

// ---------------------------------------------------------------------------
// Kernel 0: fp32 -> half conversion
// ---------------------------------------------------------------------------
__global__ void to_half_kernel(const float* __restrict__ src,
                               __half* __restrict__ dst, int n4)
{
    int i = blockIdx.x * blockDim.x + threadIdx.x;
    if (i >= n4) return;
    float4 v = ((const float4*)src)[i];
    ((__half2*)dst)[i * 2 + 0] = __floats2half2_rn(v.x, v.y);
    ((__half2*)dst)[i * 2 + 1] = __floats2half2_rn(v.z, v.w);
}

// ---------------------------------------------------------------------------
// FP16 mma GEMM (R13 config): BK=64, 3-stage, 128x128 block, 256 threads.
// ---------------------------------------------------------------------------
#define BM 128
#define BN 128
#define BK 64
#define NSTAGE 3
#define LDH 72
#define STAGE_HALVES ((BM + BN) * LDH)                  // 18432
#define STAGE_BYTES (STAGE_HALVES * 2)                  // 36864
#define GEMM_SMEM_BYTES (NSTAGE * STAGE_BYTES)          // 110592
#define CLD 136

__device__ __forceinline__
void gemm_mainloop(const __half* __restrict__ Aptr,
                   const __half* __restrict__ Bptr,
                   __half* smh, int tid, float acc[4][4][4])
{
    const int warp = tid >> 5;
    const int lane = tid & 31;
    const int wr = warp & 1;
    const int wc = warp >> 1;
    const int grp = lane >> 3;
    const int lrow = lane & 7;

    #pragma unroll
    for (int i = 0; i < 4; i++)
        #pragma unroll
        for (int j = 0; j < 4; j++)
            #pragma unroll
            for (int t = 0; t < 4; t++) acc[i][j][t] = 0.f;

    const int ldr = tid >> 3;
    const int ldc = tid & 7;

    auto prefetch = [&](int stage, int k0) {
        __half* As = smh + stage * STAGE_HALVES;
        __half* Bs = As + BM * LDH;
        #pragma unroll
        for (int p = 0; p < 4; p++) {
            const int row = p * 32 + ldr;
            cp_async16(As + row * LDH + ldc * 8,
                       Aptr + (size_t)row * CH + k0 + ldc * 8);
            cp_async16(Bs + row * LDH + ldc * 8,
                       Bptr + (size_t)row * CH + k0 + ldc * 8);
        }
    };

    prefetch(0, 0);   cp_commit();
    prefetch(1, BK);  cp_commit();

    const unsigned smbase = (unsigned)__cvta_generic_to_shared(smh);
    const unsigned a_off = ((wr * 64 + (grp & 1) * 8 + lrow) * LDH
                            + (grp >> 1) * 8) * 2;
    const unsigned b_off = (unsigned)(BM * LDH * 2)
                         + ((wc * 32 + (grp >> 1) * 8 + lrow) * LDH
                            + (grp & 1) * 8) * 2;

    const int NKT = CH / BK;     // 12
    int sC = 0, sF = 2;

    #pragma unroll 1
    for (int kt = 0; kt < NKT; kt++) {
        cp_wait<1>();
        __syncthreads();

        if (kt + 2 < NKT) prefetch(sF, (kt + 2) * BK);
        cp_commit();

        const unsigned stage_addr = smbase + sC * STAGE_BYTES;
        const unsigned a_base = stage_addr + a_off;
        const unsigned b_base = stage_addr + b_off;

        #pragma unroll
        for (int s = 0; s < 4; s++) {
            unsigned a[4][4], b[4][2];
            #pragma unroll
            for (int mi = 0; mi < 4; mi++)
                ldm_x4(a[mi][0], a[mi][1], a[mi][2], a[mi][3],
                       a_base + (mi * 16 * LDH + s * 16) * 2);
            #pragma unroll
            for (int np = 0; np < 2; np++)
                ldm_x4(b[2 * np][0], b[2 * np][1], b[2 * np + 1][0], b[2 * np + 1][1],
                       b_base + (np * 16 * LDH + s * 16) * 2);
            #pragma unroll
            for (int mi = 0; mi < 4; mi++)
                #pragma unroll
                for (int ni = 0; ni < 4; ni++)
                    mma_f16(acc[mi][ni], a[mi][0], a[mi][1], a[mi][2], a[mi][3],
                            b[ni][0], b[ni][1]);
        }
        sC = (sC + 1 == NSTAGE) ? 0 : sC + 1;
        sF = (sF + 1 == NSTAGE) ? 0 : sF + 1;
    }
}

// ---------------------------------------------------------------------------
// Kernel 1: fused QKV projection -> half q/k/v (smem-bounced stores) [R13]
// ---------------------------------------------------------------------------
__global__ __launch_bounds__(256, 2)
void qkv_gemm_kernel(const float* __restrict__ qb,
                     const float* __restrict__ vb)
{
    extern __shared__ __half smh[];
    const int bn = blockIdx.x;
    const int bm = blockIdx.y;
    const int tid = threadIdx.x;

    float acc[4][4][4];
    gemm_mainloop(g_xh + (size_t)(bm * BM) * CH, g_wh + (size_t)(bn * BN) * CH,
                  smh, tid, acc);

    const int warp = tid >> 5;
    const int lane = tid & 31;
    const int g = lane >> 2, tg = lane & 3;
    const int wr = warp & 1, wc = warp >> 1;

    const int jblock = bn * BN;
    const int which = jblock / CH;

    __syncthreads();

    #pragma unroll
    for (int mi = 0; mi < 4; mi++) {
        #pragma unroll
        for (int ni = 0; ni < 4; ni++) {
            const int jl = wc * 32 + ni * 8 + tg * 2;
            const int cbase = jblock + jl - which * CH;
            #pragma unroll
            for (int rr = 0; rr < 2; rr++) {
                const int row = wr * 64 + mi * 16 + g + rr * 8;
                const float v0 = acc[mi][ni][rr * 2 + 0];
                const float v1 = acc[mi][ni][rr * 2 + 1];
                __half2 h2;
                if (which == 0) {
                    float2 qb2 = *(const float2*)(qb + cbase);
                    h2 = __floats2half2_rn((v0 + qb2.x) * SCALE, (v1 + qb2.y) * SCALE);
                } else if (which == 1) {
                    h2 = __floats2half2_rn(v0, v1);
                } else {
                    float2 vb2 = *(const float2*)(vb + cbase);
                    h2 = __floats2half2_rn(v0 + vb2.x, v1 + vb2.y);
                }
                *(__half2*)(smh + row * CLD + jl) = h2;
            }
        }
    }
    __syncthreads();

    __half* dstT = (which == 0) ? g_q : (which == 1) ? g_k : g_v;
    #pragma unroll
    for (int it = 0; it < 8; it++) {
        const int idx = tid + it * 256;
        const int r = idx >> 4;
        const int cb = (idx & 15) * 8;
        const int cbase = jblock + cb - which * CH;
        const int h = cbase >> 6;
        const int d = cbase & 63;
        const int m = bm * BM + r;
        const int b = m / SEQ;
        const int n = m - b * SEQ;
        const uint4 val = *(const uint4*)(smh + r * CLD + cb);
        *(uint4*)(dstT + (((size_t)(b * NH + h)) * SEQ + n) * HD + d) = val;
    }
}

// ---------------------------------------------------------------------------
// Kernel 2: rpb gather -> half, padded [H][196][208]
// ---------------------------------------------------------------------------
__global__ void rpb_gather_kernel(const float* __restrict__ table,
                                  const int* __restrict__ relidx)
{
    int idx = blockIdx.x * blockDim.x + threadIdx.x;
    const int total = NH * SEQ * RPB_LD;
    if (idx >= total) return;
    const int h = idx / (SEQ * RPB_LD);
    const int rem = idx - h * SEQ * RPB_LD;
    const int i = rem / RPB_LD;
    const int j = rem - i * RPB_LD;
    __half v = __float2half(0.f);
    if (j < SEQ) v = __float2half(table[relidx[i * SEQ + j] * NH + h]);
    g_rpbh[idx] = v;
}

// ---------------------------------------------------------------------------
// Kernel 3: FP16 mma attention with ldmatrix fragment loads.
// Ks [208][72], Vt [64][216], P [128][216] (overlay Q [128][72]), RB [128][216].
// ---------------------------------------------------------------------------
#define LQ 72
#define LV 216
#define LP 216
#define RB_LD 216
#define KROWS 208
#define KOFFH (128 * LP)                  // 27648
#define VOFFH (KOFFH + KROWS * LQ)        // 42624
#define RBOFFH (VOFFH + 64 * LV)          // 56448
#define AT_SMEM_BYTES ((RBOFFH + 128 * RB_LD) * 2)   // 168192 bytes

__global__ __launch_bounds__(256, 1)
void attn_mma_kernel()
{
    extern __shared__ __half smh[];
    __half* P  = smh;                // [128][LP]
    __half* Qs = smh;                // [128][LQ] overlay
    __half* Ks = smh + KOFFH;        // [KROWS][LQ]
    __half* Vt = smh + VOFFH;        // [64][LV] transposed V
    __half* RB = smh + RBOFFH;       // [128][RB_LD] rpb tile

    const int bh = blockIdx.x;
    const int b = bh / NH;
    const int h = bh % NH;
    const int tid = threadIdx.x;
    const int warp = tid >> 5;
    const int lane = tid & 31;
    const int g = lane >> 2;
    const int tg = lane & 3;
    const int grp = lane >> 3;
    const int lrow = lane & 7;

    const __half* Qg = g_q + (size_t)bh * SEQ * HD;
    const __half* Kg = g_k + (size_t)bh * SEQ * HD;
    const __half* Vg = g_v + (size_t)bh * SEQ * HD;
    const __half* rpbh = g_rpbh + (size_t)h * SEQ * RPB_LD;

    const uint4 z16 = make_uint4(0, 0, 0, 0);

    // stage K [208 rows] (zero rows 196..207)
    for (int t = tid; t < KROWS * 8; t += 256) {
        const int r = t >> 3, c = (t & 7) * 8;
        if (r < SEQ) cp_async16(Ks + r * LQ + c, Kg + r * HD + c);
        else         *(uint4*)(Ks + r * LQ + c) = z16;
    }
    // stage V transposed [d][key]
    for (int t = tid; t < SEQ * 8; t += 256) {
        const int key = t >> 3, d0 = (t & 7) * 8;
        const uint4 raw = *(const uint4*)(Vg + key * HD + d0);
        const __half* hp = (const __half*)&raw;
        #pragma unroll
        for (int j = 0; j < 8; j++)
            Vt[(d0 + j) * LV + key] = hp[j];
    }
    for (int t = tid; t < 64 * 20; t += 256) {
        const int d = t / 20, kk = SEQ + t % 20;
        Vt[d * LV + kk] = __ushort_as_half((unsigned short)0);
    }
    cp_commit();

    __half* attbase = g_att + (size_t)b * SEQ * CH + h * HD;

    const unsigned smb = (unsigned)__cvta_generic_to_shared(smh);
    const int r0 = warp * 16;
    // ldmatrix bases (bytes)
    const unsigned q_base = smb + ((r0 + (grp & 1) * 8 + lrow) * LQ
                                   + (grp >> 1) * 8) * 2;
    const unsigned k_base = smb + (unsigned)(KOFFH * 2)
                          + (((grp >> 1) * 8 + lrow) * LQ + (grp & 1) * 8) * 2;
    const unsigned p_base = smb + ((r0 + (grp & 1) * 8 + lrow) * LP
                                   + (grp >> 1) * 8) * 2;
    const unsigned v_base = smb + (unsigned)(VOFFH * 2)
                          + (((grp >> 1) * 8 + lrow) * LV + (grp & 1) * 8) * 2;

    #pragma unroll 1
    for (int mt = 0; mt < 2; mt++) {
        const int qbase = mt * 128;
        const int qrows = mt ? (SEQ - 128) : 128;

        __syncthreads();
        for (int t = tid; t < 128 * 8; t += 256) {
            const int r = t >> 3, c = (t & 7) * 8;
            if (r < qrows)
                cp_async16(Qs + r * LQ + c, Qg + (qbase + r) * HD + c);
            else
                *(uint4*)(Qs + r * LQ + c) = z16;
        }
        for (int t = tid; t < 128 * 26; t += 256) {
            const int r = t / 26, ch = (t % 26) * 8;
            if (r < qrows)
                cp_async16(RB + r * RB_LD + ch,
                           rpbh + (size_t)(qbase + r) * RPB_LD + ch);
            else
                *(uint4*)(RB + r * RB_LD + ch) = z16;
        }
        cp_commit();
        cp_wait<0>();
        __syncthreads();

        // ---- Phase 1: S = Q @ K^T (ldmatrix; 26 n-tiles over 208 keys) ----
        float acc[26][4];
        #pragma unroll
        for (int t = 0; t < 26; t++)
            #pragma unroll
            for (int e = 0; e < 4; e++) acc[t][e] = 0.f;

        #pragma unroll
        for (int ks = 0; ks < 4; ks++) {
            const int k0 = ks * 16;
            unsigned a0, a1, a2, a3;
            ldm_x4(a0, a1, a2, a3, q_base + k0 * 2);
            #pragma unroll
            for (int tp = 0; tp < 13; tp++) {
                unsigned b0, b1, b2, b3;
                ldm_x4(b0, b1, b2, b3, k_base + (tp * 16 * LQ + k0) * 2);
                mma_f16(acc[2 * tp + 0], a0, a1, a2, a3, b0, b1);
                mma_f16(acc[2 * tp + 1], a0, a1, a2, a3, b2, b3);
            }
        }
        __syncthreads();   // Q reads done (P overlays Q)

        // ---- rpb add + masking ----
        const int rlo = qbase + r0 + g;
        const int rhi = rlo + 8;
        const __half* RBlo = RB + (r0 + g) * RB_LD;
        const __half* RBhi = RB + (r0 + g + 8) * RB_LD;
        #pragma unroll
        for (int t = 0; t < 26; t++) {
            const int c0 = t * 8 + 2 * tg;
            const float2 flo = __half22float2(*(const __half2*)(RBlo + c0));
            const float2 fhi = __half22float2(*(const __half2*)(RBhi + c0));
            if (c0 < SEQ)     { acc[t][0] += flo.x; acc[t][2] += fhi.x; }
            else              { acc[t][0] = -1e30f; acc[t][2] = -1e30f; }
            if (c0 + 1 < SEQ) { acc[t][1] += flo.y; acc[t][3] += fhi.y; }
            else              { acc[t][1] = -1e30f; acc[t][3] = -1e30f; }
        }

        // ---- softmax ----
        float mlo = -1e30f, mhi = -1e30f;
        #pragma unroll
        for (int t = 0; t < 26; t++) {
            mlo = fmaxf(mlo, fmaxf(acc[t][0], acc[t][1]));
            mhi = fmaxf(mhi, fmaxf(acc[t][2], acc[t][3]));
        }
        mlo = fmaxf(mlo, __shfl_xor_sync(0xffffffffu, mlo, 1));
        mlo = fmaxf(mlo, __shfl_xor_sync(0xffffffffu, mlo, 2));
        mhi = fmaxf(mhi, __shfl_xor_sync(0xffffffffu, mhi, 1));
        mhi = fmaxf(mhi, __shfl_xor_sync(0xffffffffu, mhi, 2));

        float llo = 0.f, lhi = 0.f;
        __half* Prow_lo = P + (r0 + g) * LP;
        __half* Prow_hi = P + (r0 + g + 8) * LP;
        #pragma unroll
        for (int t = 0; t < 26; t++) {
            const int c0 = t * 8 + 2 * tg;
            const __half2 p01 = __floats2half2_rn(__expf(acc[t][0] - mlo),
                                                  __expf(acc[t][1] - mlo));
            const __half2 p23 = __floats2half2_rn(__expf(acc[t][2] - mhi),
                                                  __expf(acc[t][3] - mhi));
            const float2 f01 = __half22float2(p01);
            const float2 f23 = __half22float2(p23);
            llo += f01.x + f01.y;
            lhi += f23.x + f23.y;
            *(__half2*)(Prow_lo + c0) = p01;
            *(__half2*)(Prow_hi + c0) = p23;
        }

        llo += __shfl_xor_sync(0xffffffffu, llo, 1);
        llo += __shfl_xor_sync(0xffffffffu, llo, 2);
        lhi += __shfl_xor_sync(0xffffffffu, lhi, 1);
        lhi += __shfl_xor_sync(0xffffffffu, lhi, 2);
        const float inv_lo = 1.f / llo;
        const float inv_hi = 1.f / lhi;

        __syncwarp();   // own P rows complete (only own rows read back)

        // ---- Phase 2: O = P @ V (ldmatrix; 13 k16 steps over 208 keys) ----
        float oacc[8][4];
        #pragma unroll
        for (int nt = 0; nt < 8; nt++)
            #pragma unroll
            for (int e = 0; e < 4; e++) oacc[nt][e] = 0.f;

        #pragma unroll
        for (int kt = 0; kt < 13; kt++) {
            const int k0 = kt * 16;
            unsigned a0, a1, a2, a3;
            ldm_x4(a0, a1, a2, a3, p_base + k0 * 2);
            #pragma unroll
            for (int ntp = 0; ntp < 4; ntp++) {
                unsigned b0, b1, b2, b3;
                ldm_x4(b0, b1, b2, b3, v_base + (ntp * 16 * LV + k0) * 2);
                mma_f16(oacc[2 * ntp + 0], a0, a1, a2, a3, b0, b1);
                mma_f16(oacc[2 * ntp + 1], a0, a1, a2, a3, b2, b3);
            }
        }

        // ---- store O as half ----
        #pragma unroll
        for (int nt = 0; nt < 8; nt++) {
            const int c = nt * 8 + 2 * tg;
            if (rlo < SEQ)
                *(__half2*)(attbase + (size_t)rlo * CH + c) =
                    __floats2half2_rn(oacc[nt][0] * inv_lo, oacc[nt][1] * inv_lo);
            if (rhi < SEQ)
                *(__half2*)(attbase + (size_t)rhi * CH + c) =
                    __floats2half2_rn(oacc[nt][2] * inv_hi, oacc[nt][3] * inv_hi);
        }
    }
}

// ---------------------------------------------------------------------------
// Kernel 4: output projection [R13]
// ---------------------------------------------------------------------------
__global__ __launch_bounds__(256, 2)
void proj_gemm_kernel(const float* __restrict__ pb,
                      float* __restrict__ out)
{
    extern __shared__ __half smh[];
    const int bn = blockIdx.x;
    const int bm = blockIdx.y;
    const int tid = threadIdx.x;

    float acc[4][4][4];
    gemm_mainloop(g_att + (size_t)(bm * BM) * CH, g_pwh + (size_t)(bn * BN) * CH,
                  smh, tid, acc);

    const int warp = tid >> 5;
    const int lane = tid & 31;
    const int g = lane >> 2, tg = lane & 3;
    const int wr = warp & 1, wc = warp >> 1;

    #pragma unroll
    for (int mi = 0; mi < 4; mi++) {
        #pragma unroll
        for (int ni = 0; ni < 4; ni++) {
            const int j = bn * BN + wc * 32 + ni * 8 + tg * 2;
            const float2 pb2 = *(const float2*)(pb + j);
            #pragma unroll
            for (int rr = 0; rr < 2; rr++) {
                const int i = bm * BM + wr * 64 + mi * 16 + g + rr * 8;
                float2 o2;
                o2.x = acc[mi][ni][rr * 2 + 0] + pb2.x;
                o2.y = acc[mi][ni][rr * 2 + 1] + pb2.y;
                *(float2*)(out + (size_t)i * CH + j) = o2;
            }
        }
    }
}

// ---------------------------------------------------------------------------
// Launch
// ---------------------------------------------------------------------------
extern "C" void kernel_launch(void* const* d_in, const int* in_sizes, int n_in,
                              void* d_out, int out_size)
{
    const float* x       = (const float*)d_in[0];
    const float* qkv_w   = (const float*)d_in[1];
    const float* q_bias  = (const float*)d_in[2];
    const float* v_bias  = (const float*)d_in[3];
    const float* rpb_tab = (const float*)d_in[4];
    const float* proj_w  = (const float*)d_in[5];
    const float* proj_b  = (const float*)d_in[6];
    const int*   relidx  = (const int*)d_in[7];
    float*       out     = (float*)d_out;

    static bool attrs_set = false;
    if (!attrs_set) {
        cudaFuncSetAttribute(qkv_gemm_kernel,
                             cudaFuncAttributeMaxDynamicSharedMemorySize,
                             GEMM_SMEM_BYTES);
        cudaFuncSetAttribute(proj_gemm_kernel,
                             cudaFuncAttributeMaxDynamicSharedMemorySize,
                             GEMM_SMEM_BYTES);
        cudaFuncSetAttribute(attn_mma_kernel,
                             cudaFuncAttributeMaxDynamicSharedMemorySize,
                             AT_SMEM_BYTES);
        attrs_set = true;
    }

    __half* xh_p;  cudaGetSymbolAddress((void**)&xh_p,  g_xh);
    __half* wh_p;  cudaGetSymbolAddress((void**)&wh_p,  g_wh);
    __half* pwh_p; cudaGetSymbolAddress((void**)&pwh_p, g_pwh);

    // 0. Convert GEMM operands to half
    {
        int n4 = (M_ROWS * CH) / 4;
        to_half_kernel<<<(n4 + 255) / 256, 256>>>(x, xh_p, n4);
        n4 = (THREE_C * CH) / 4;
        to_half_kernel<<<(n4 + 255) / 256, 256>>>(qkv_w, wh_p, n4);
        n4 = (CH * CH) / 4;
        to_half_kernel<<<(n4 + 255) / 256, 256>>>(proj_w, pwh_p, n4);
    }
    // 1. QKV projection
    {
        dim3 grid(THREE_C / BN, M_ROWS / BM);   // (18, 392)
        qkv_gemm_kernel<<<grid, 256, GEMM_SMEM_BYTES>>>(q_bias, v_bias);
    }
    // 2. RPB gather (half, padded)
    {
        const int total = NH * SEQ * RPB_LD;
        rpb_gather_kernel<<<(total + 255) / 256, 256>>>(rpb_tab, relidx);
    }
    // 3. Attention (fp16 mma + ldmatrix)
    {
        attn_mma_kernel<<<BATCH * NH, 256, AT_SMEM_BYTES>>>();
    }
    // 4. Projection
    {
        dim3 grid(CH / BN, M_ROWS / BM);        // (6, 392)
        proj_gemm_kernel<<<grid, 256, GEMM_SMEM_BYTES>>>(proj_b, out);
    }
}

// round 16
// speedup vs baseline: 1.0857x; 1.0597x over previous
#include <cuda_runtime.h>
#include <cuda_bf16.h>
#include <cuda_fp16.h>

// Problem constants
#define BATCH 256
#define SEQ   196
#define CH    768
#define NH    12
#define HD    64
#define M_ROWS (BATCH * SEQ)       // 50176
#define THREE_C (3 * CH)           // 2304
#define SCALE 0.125f
#define RPB_LD 208                 // padded rpb row length (halves)

// Scratch (q/k/v half, [B,H,N,hd])
__device__ __half g_q[(size_t)BATCH * NH * SEQ * HD];
__device__ __half g_k[(size_t)BATCH * NH * SEQ * HD];
__device__ __half g_v[(size_t)BATCH * NH * SEQ * HD];
__device__ __half g_rpbh[(size_t)NH * SEQ * RPB_LD];   // [H,196,208] half
__device__ __half g_att[(size_t)M_ROWS * CH];          // [B,N,C] half
__device__ __half g_xh[(size_t)M_ROWS * CH];
__device__ __half g_wh[(size_t)THREE_C * CH];
__device__ __half g_pwh[(size_t)CH * CH];

// ---------------------------------------------------------------------------
// PTX helpers
// ---------------------------------------------------------------------------
__device__ __forceinline__ void cp_async16(void* smem_ptr, const void* gmem_ptr) {
    unsigned saddr = (unsigned)__cvta_generic_to_shared(smem_ptr);
    asm volatile("cp.async.cg.shared.global [%0], [%1], 16;\n"
                 :: "r"(saddr), "l"(gmem_ptr));
}
__device__ __forceinline__ void cp_commit() {
    asm volatile("cp.async.commit_group;\n");
}
template <int N>
__device__ __forceinline__ void cp_wait() {
    asm volatile("cp.async.wait_group %0;\n" :: "n"(N));
}
__device__ __forceinline__ void mma_f16(float c[4], unsigned a0, unsigned a1,
                                        unsigned a2, unsigned a3,
                                        unsigned b0, unsigned b1) {
    asm volatile(
        "mma.sync.aligned.m16n8k16.row.col.f32.f16.f16.f32 "
        "{%0,%1,%2,%3}, {%4,%5,%6,%7}, {%8,%9}, {%0,%1,%2,%3};\n"
        : "+f"(c[0]), "+f"(c[1]), "+f"(c[2]), "+f"(c[3])
        : "r"(a0), "r"(a1), "r"(a2), "r"(a3), "r"(b0), "r"(b1));
}
__device__ __forceinline__ void ldm_x4(unsigned& r0, unsigned& r1,
                                       unsigned& r2, unsigned& r3, unsigned addr) {
    asm volatile("ldmatrix.sync.aligned.m8n8.x4.shared.b16 {%0,%1,%2,%3}, [%4];"
                 : "=r"(r0), "=r"(r1), "=r"(r2), "=r"(r3) : "r"(addr));
}

// ---------------------------------------------------------------------------
// Kernel 0: fp32 -> half conversion
// ---------------------------------------------------------------------------
__global__ void to_half_kernel(const float* __restrict__ src,
                               __half* __restrict__ dst, int n4)
{
    int i = blockIdx.x * blockDim.x + threadIdx.x;
    if (i >= n4) return;
    float4 v = ((const float4*)src)[i];
    ((__half2*)dst)[i * 2 + 0] = __floats2half2_rn(v.x, v.y);
    ((__half2*)dst)[i * 2 + 1] = __floats2half2_rn(v.z, v.w);
}

// ---------------------------------------------------------------------------
// FP16 mma GEMM (frozen R13 config): BK=64, 3-stage, 128x128, 256 threads.
// ---------------------------------------------------------------------------
#define BM 128
#define BN 128
#define BK 64
#define NSTAGE 3
#define LDH 72
#define STAGE_HALVES ((BM + BN) * LDH)                  // 18432
#define STAGE_BYTES (STAGE_HALVES * 2)                  // 36864
#define GEMM_SMEM_BYTES (NSTAGE * STAGE_BYTES)          // 110592
#define CLD 136

__device__ __forceinline__
void gemm_mainloop(const __half* __restrict__ Aptr,
                   const __half* __restrict__ Bptr,
                   __half* smh, int tid, float acc[4][4][4])
{
    const int warp = tid >> 5;
    const int lane = tid & 31;
    const int wr = warp & 1;
    const int wc = warp >> 1;
    const int grp = lane >> 3;
    const int lrow = lane & 7;

    #pragma unroll
    for (int i = 0; i < 4; i++)
        #pragma unroll
        for (int j = 0; j < 4; j++)
            #pragma unroll
            for (int t = 0; t < 4; t++) acc[i][j][t] = 0.f;

    const int ldr = tid >> 3;
    const int ldc = tid & 7;

    auto prefetch = [&](int stage, int k0) {
        __half* As = smh + stage * STAGE_HALVES;
        __half* Bs = As + BM * LDH;
        #pragma unroll
        for (int p = 0; p < 4; p++) {
            const int row = p * 32 + ldr;
            cp_async16(As + row * LDH + ldc * 8,
                       Aptr + (size_t)row * CH + k0 + ldc * 8);
            cp_async16(Bs + row * LDH + ldc * 8,
                       Bptr + (size_t)row * CH + k0 + ldc * 8);
        }
    };

    prefetch(0, 0);   cp_commit();
    prefetch(1, BK);  cp_commit();

    const unsigned smbase = (unsigned)__cvta_generic_to_shared(smh);
    const unsigned a_off = ((wr * 64 + (grp & 1) * 8 + lrow) * LDH
                            + (grp >> 1) * 8) * 2;
    const unsigned b_off = (unsigned)(BM * LDH * 2)
                         + ((wc * 32 + (grp >> 1) * 8 + lrow) * LDH
                            + (grp & 1) * 8) * 2;

    const int NKT = CH / BK;     // 12
    int sC = 0, sF = 2;

    #pragma unroll 1
    for (int kt = 0; kt < NKT; kt++) {
        cp_wait<1>();
        __syncthreads();

        if (kt + 2 < NKT) prefetch(sF, (kt + 2) * BK);
        cp_commit();

        const unsigned stage_addr = smbase + sC * STAGE_BYTES;
        const unsigned a_base = stage_addr + a_off;
        const unsigned b_base = stage_addr + b_off;

        #pragma unroll
        for (int s = 0; s < 4; s++) {
            unsigned a[4][4], b[4][2];
            #pragma unroll
            for (int mi = 0; mi < 4; mi++)
                ldm_x4(a[mi][0], a[mi][1], a[mi][2], a[mi][3],
                       a_base + (mi * 16 * LDH + s * 16) * 2);
            #pragma unroll
            for (int np = 0; np < 2; np++)
                ldm_x4(b[2 * np][0], b[2 * np][1], b[2 * np + 1][0], b[2 * np + 1][1],
                       b_base + (np * 16 * LDH + s * 16) * 2);
            #pragma unroll
            for (int mi = 0; mi < 4; mi++)
                #pragma unroll
                for (int ni = 0; ni < 4; ni++)
                    mma_f16(acc[mi][ni], a[mi][0], a[mi][1], a[mi][2], a[mi][3],
                            b[ni][0], b[ni][1]);
        }
        sC = (sC + 1 == NSTAGE) ? 0 : sC + 1;
        sF = (sF + 1 == NSTAGE) ? 0 : sF + 1;
    }
}

// ---------------------------------------------------------------------------
// Kernel 1: fused QKV projection (frozen R13)
// ---------------------------------------------------------------------------
__global__ __launch_bounds__(256, 2)
void qkv_gemm_kernel(const float* __restrict__ qb,
                     const float* __restrict__ vb)
{
    extern __shared__ __half smh[];
    const int bn = blockIdx.x;
    const int bm = blockIdx.y;
    const int tid = threadIdx.x;

    float acc[4][4][4];
    gemm_mainloop(g_xh + (size_t)(bm * BM) * CH, g_wh + (size_t)(bn * BN) * CH,
                  smh, tid, acc);

    const int warp = tid >> 5;
    const int lane = tid & 31;
    const int g = lane >> 2, tg = lane & 3;
    const int wr = warp & 1, wc = warp >> 1;

    const int jblock = bn * BN;
    const int which = jblock / CH;

    __syncthreads();

    #pragma unroll
    for (int mi = 0; mi < 4; mi++) {
        #pragma unroll
        for (int ni = 0; ni < 4; ni++) {
            const int jl = wc * 32 + ni * 8 + tg * 2;
            const int cbase = jblock + jl - which * CH;
            #pragma unroll
            for (int rr = 0; rr < 2; rr++) {
                const int row = wr * 64 + mi * 16 + g + rr * 8;
                const float v0 = acc[mi][ni][rr * 2 + 0];
                const float v1 = acc[mi][ni][rr * 2 + 1];
                __half2 h2;
                if (which == 0) {
                    float2 qb2 = *(const float2*)(qb + cbase);
                    h2 = __floats2half2_rn((v0 + qb2.x) * SCALE, (v1 + qb2.y) * SCALE);
                } else if (which == 1) {
                    h2 = __floats2half2_rn(v0, v1);
                } else {
                    float2 vb2 = *(const float2*)(vb + cbase);
                    h2 = __floats2half2_rn(v0 + vb2.x, v1 + vb2.y);
                }
                *(__half2*)(smh + row * CLD + jl) = h2;
            }
        }
    }
    __syncthreads();

    __half* dstT = (which == 0) ? g_q : (which == 1) ? g_k : g_v;
    #pragma unroll
    for (int it = 0; it < 8; it++) {
        const int idx = tid + it * 256;
        const int r = idx >> 4;
        const int cb = (idx & 15) * 8;
        const int cbase = jblock + cb - which * CH;
        const int h = cbase >> 6;
        const int d = cbase & 63;
        const int m = bm * BM + r;
        const int b = m / SEQ;
        const int n = m - b * SEQ;
        const uint4 val = *(const uint4*)(smh + r * CLD + cb);
        *(uint4*)(dstT + (((size_t)(b * NH + h)) * SEQ + n) * HD + d) = val;
    }
}

// ---------------------------------------------------------------------------
// Kernel 2: rpb gather -> half, padded [H][196][208]
// ---------------------------------------------------------------------------
__global__ void rpb_gather_kernel(const float* __restrict__ table,
                                  const int* __restrict__ relidx)
{
    int idx = blockIdx.x * blockDim.x + threadIdx.x;
    const int total = NH * SEQ * RPB_LD;
    if (idx >= total) return;
    const int h = idx / (SEQ * RPB_LD);
    const int rem = idx - h * SEQ * RPB_LD;
    const int i = rem / RPB_LD;
    const int j = rem - i * RPB_LD;
    __half v = __float2half(0.f);
    if (j < SEQ) v = __float2half(table[relidx[i * SEQ + j] * NH + h]);
    g_rpbh[idx] = v;
}

// ---------------------------------------------------------------------------
// Kernel 3: FP16 mma attention, single-pass, 448 threads (14 warps).
// Qs [208][72], Ks [208][72], Vt [64][216], P [208][216]. rpb via __ldg.
// ---------------------------------------------------------------------------
#define NT_AT 448
#define LQ 72
#define LV 216
#define LP 216
#define KROWS 208
#define AQ_OFF 0
#define AK_OFF (KROWS * LQ)               // 14976
#define AV_OFF (AK_OFF + KROWS * LQ)      // 29952
#define AP_OFF (AV_OFF + 64 * LV)         // 43776
#define AT_SMEM_HALVES (AP_OFF + KROWS * LP)   // 88704
#define AT_SMEM_BYTES (AT_SMEM_HALVES * 2)     // 177408

__global__ __launch_bounds__(NT_AT, 1)
void attn_mma_kernel()
{
    extern __shared__ __half smh[];
    __half* Qs = smh + AQ_OFF;       // [208][72]
    __half* Ks = smh + AK_OFF;       // [208][72]
    __half* Vt = smh + AV_OFF;       // [64][216]
    __half* P  = smh + AP_OFF;       // [208][216]

    const int bh = blockIdx.x;
    const int b = bh / NH;
    const int h = bh % NH;
    const int tid = threadIdx.x;
    const int warp = tid >> 5;
    const int lane = tid & 31;
    const int g = lane >> 2;
    const int tg = lane & 3;
    const int grp = lane >> 3;
    const int lrow = lane & 7;

    const __half* Qg = g_q + (size_t)bh * SEQ * HD;
    const __half* Kg = g_k + (size_t)bh * SEQ * HD;
    const __half* Vg = g_v + (size_t)bh * SEQ * HD;
    const __half* rpbh = g_rpbh + (size_t)h * SEQ * RPB_LD;

    const uint4 z16 = make_uint4(0, 0, 0, 0);

    // stage Q and K [208 rows x 8 chunks] (zero rows 196..207)
    for (int t = tid; t < KROWS * 8; t += NT_AT) {
        const int r = t >> 3, c = (t & 7) * 8;
        if (r < SEQ) {
            cp_async16(Qs + r * LQ + c, Qg + r * HD + c);
            cp_async16(Ks + r * LQ + c, Kg + r * HD + c);
        } else {
            *(uint4*)(Qs + r * LQ + c) = z16;
            *(uint4*)(Ks + r * LQ + c) = z16;
        }
    }
    // stage V transposed [d][key]
    for (int t = tid; t < SEQ * 8; t += NT_AT) {
        const int key = t >> 3, d0 = (t & 7) * 8;
        const uint4 raw = *(const uint4*)(Vg + key * HD + d0);
        const __half* hp = (const __half*)&raw;
        #pragma unroll
        for (int j = 0; j < 8; j++)
            Vt[(d0 + j) * LV + key] = hp[j];
    }
    for (int t = tid; t < 64 * 20; t += NT_AT) {
        const int d = t / 20, kk = SEQ + t % 20;
        Vt[d * LV + kk] = __ushort_as_half((unsigned short)0);
    }
    cp_commit();
    cp_wait<0>();
    __syncthreads();

    if (warp >= 13) return;   // warps 0..12 compute rows 0..207

    __half* attbase = g_att + (size_t)b * SEQ * CH + h * HD;

    const unsigned smb = (unsigned)__cvta_generic_to_shared(smh);
    const int r0 = warp * 16;
    const unsigned q_base = smb + (unsigned)(AQ_OFF * 2)
                          + ((r0 + (grp & 1) * 8 + lrow) * LQ + (grp >> 1) * 8) * 2;
    const unsigned k_base = smb + (unsigned)(AK_OFF * 2)
                          + (((grp >> 1) * 8 + lrow) * LQ + (grp & 1) * 8) * 2;
    const unsigned p_base = smb + (unsigned)(AP_OFF * 2)
                          + ((r0 + (grp & 1) * 8 + lrow) * LP + (grp >> 1) * 8) * 2;
    const unsigned v_base = smb + (unsigned)(AV_OFF * 2)
                          + (((grp >> 1) * 8 + lrow) * LV + (grp & 1) * 8) * 2;

    // ---- Phase 1: S = Q @ K^T (26 n-tiles over 208 keys) ----
    float acc[26][4];
    #pragma unroll
    for (int t = 0; t < 26; t++)
        #pragma unroll
        for (int e = 0; e < 4; e++) acc[t][e] = 0.f;

    #pragma unroll
    for (int ks = 0; ks < 4; ks++) {
        const int k0 = ks * 16;
        unsigned a0, a1, a2, a3;
        ldm_x4(a0, a1, a2, a3, q_base + k0 * 2);
        #pragma unroll
        for (int tp = 0; tp < 13; tp++) {
            unsigned b0, b1, b2, b3;
            ldm_x4(b0, b1, b2, b3, k_base + (tp * 16 * LQ + k0) * 2);
            mma_f16(acc[2 * tp + 0], a0, a1, a2, a3, b0, b1);
            mma_f16(acc[2 * tp + 1], a0, a1, a2, a3, b2, b3);
        }
    }

    // ---- rpb add (direct ldg, half2) + masking ----
    const int rlo = r0 + g;
    const int rhi = rlo + 8;
    const __half* rp_lo = rpbh + (size_t)min(rlo, SEQ - 1) * RPB_LD;
    const __half* rp_hi = rpbh + (size_t)min(rhi, SEQ - 1) * RPB_LD;
    #pragma unroll
    for (int t = 0; t < 26; t++) {
        const int c0 = t * 8 + 2 * tg;
        const float2 flo = __half22float2(__ldg((const __half2*)(rp_lo + c0)));
        const float2 fhi = __half22float2(__ldg((const __half2*)(rp_hi + c0)));
        if (c0 < SEQ)     { acc[t][0] += flo.x; acc[t][2] += fhi.x; }
        else              { acc[t][0] = -1e30f; acc[t][2] = -1e30f; }
        if (c0 + 1 < SEQ) { acc[t][1] += flo.y; acc[t][3] += fhi.y; }
        else              { acc[t][1] = -1e30f; acc[t][3] = -1e30f; }
    }

    // ---- softmax ----
    float mlo = -1e30f, mhi = -1e30f;
    #pragma unroll
    for (int t = 0; t < 26; t++) {
        mlo = fmaxf(mlo, fmaxf(acc[t][0], acc[t][1]));
        mhi = fmaxf(mhi, fmaxf(acc[t][2], acc[t][3]));
    }
    mlo = fmaxf(mlo, __shfl_xor_sync(0xffffffffu, mlo, 1));
    mlo = fmaxf(mlo, __shfl_xor_sync(0xffffffffu, mlo, 2));
    mhi = fmaxf(mhi, __shfl_xor_sync(0xffffffffu, mhi, 1));
    mhi = fmaxf(mhi, __shfl_xor_sync(0xffffffffu, mhi, 2));

    float llo = 0.f, lhi = 0.f;
    __half* Prow_lo = P + (r0 + g) * LP;
    __half* Prow_hi = P + (r0 + g + 8) * LP;
    #pragma unroll
    for (int t = 0; t < 26; t++) {
        const int c0 = t * 8 + 2 * tg;
        const __half2 p01 = __floats2half2_rn(__expf(acc[t][0] - mlo),
                                              __expf(acc[t][1] - mlo));
        const __half2 p23 = __floats2half2_rn(__expf(acc[t][2] - mhi),
                                              __expf(acc[t][3] - mhi));
        const float2 f01 = __half22float2(p01);
        const float2 f23 = __half22float2(p23);
        llo += f01.x + f01.y;
        lhi += f23.x + f23.y;
        *(__half2*)(Prow_lo + c0) = p01;
        *(__half2*)(Prow_hi + c0) = p23;
    }

    llo += __shfl_xor_sync(0xffffffffu, llo, 1);
    llo += __shfl_xor_sync(0xffffffffu, llo, 2);
    lhi += __shfl_xor_sync(0xffffffffu, lhi, 1);
    lhi += __shfl_xor_sync(0xffffffffu, lhi, 2);
    const float inv_lo = 1.f / llo;
    const float inv_hi = 1.f / lhi;

    __syncwarp();   // own P rows complete (only own rows read back)

    // ---- Phase 2: O = P @ V (13 k16 steps over 208 keys) ----
    float oacc[8][4];
    #pragma unroll
    for (int nt = 0; nt < 8; nt++)
        #pragma unroll
        for (int e = 0; e < 4; e++) oacc[nt][e] = 0.f;

    #pragma unroll
    for (int kt = 0; kt < 13; kt++) {
        const int k0 = kt * 16;
        unsigned a0, a1, a2, a3;
        ldm_x4(a0, a1, a2, a3, p_base + k0 * 2);
        #pragma unroll
        for (int ntp = 0; ntp < 4; ntp++) {
            unsigned b0, b1, b2, b3;
            ldm_x4(b0, b1, b2, b3, v_base + (ntp * 16 * LV + k0) * 2);
            mma_f16(oacc[2 * ntp + 0], a0, a1, a2, a3, b0, b1);
            mma_f16(oacc[2 * ntp + 1], a0, a1, a2, a3, b2, b3);
        }
    }

    // ---- store O as half ----
    #pragma unroll
    for (int nt = 0; nt < 8; nt++) {
        const int c = nt * 8 + 2 * tg;
        if (rlo < SEQ)
            *(__half2*)(attbase + (size_t)rlo * CH + c) =
                __floats2half2_rn(oacc[nt][0] * inv_lo, oacc[nt][1] * inv_lo);
        if (rhi < SEQ)
            *(__half2*)(attbase + (size_t)rhi * CH + c) =
                __floats2half2_rn(oacc[nt][2] * inv_hi, oacc[nt][3] * inv_hi);
    }
}

// ---------------------------------------------------------------------------
// Kernel 4: output projection (frozen R13)
// ---------------------------------------------------------------------------
__global__ __launch_bounds__(256, 2)
void proj_gemm_kernel(const float* __restrict__ pb,
                      float* __restrict__ out)
{
    extern __shared__ __half smh[];
    const int bn = blockIdx.x;
    const int bm = blockIdx.y;
    const int tid = threadIdx.x;

    float acc[4][4][4];
    gemm_mainloop(g_att + (size_t)(bm * BM) * CH, g_pwh + (size_t)(bn * BN) * CH,
                  smh, tid, acc);

    const int warp = tid >> 5;
    const int lane = tid & 31;
    const int g = lane >> 2, tg = lane & 3;
    const int wr = warp & 1, wc = warp >> 1;

    #pragma unroll
    for (int mi = 0; mi < 4; mi++) {
        #pragma unroll
        for (int ni = 0; ni < 4; ni++) {
            const int j = bn * BN + wc * 32 + ni * 8 + tg * 2;
            const float2 pb2 = *(const float2*)(pb + j);
            #pragma unroll
            for (int rr = 0; rr < 2; rr++) {
                const int i = bm * BM + wr * 64 + mi * 16 + g + rr * 8;
                float2 o2;
                o2.x = acc[mi][ni][rr * 2 + 0] + pb2.x;
                o2.y = acc[mi][ni][rr * 2 + 1] + pb2.y;
                *(float2*)(out + (size_t)i * CH + j) = o2;
            }
        }
    }
}

// ---------------------------------------------------------------------------
// Launch
// ---------------------------------------------------------------------------
extern "C" void kernel_launch(void* const* d_in, const int* in_sizes, int n_in,
                              void* d_out, int out_size)
{
    const float* x       = (const float*)d_in[0];
    const float* qkv_w   = (const float*)d_in[1];
    const float* q_bias  = (const float*)d_in[2];
    const float* v_bias  = (const float*)d_in[3];
    const float* rpb_tab = (const float*)d_in[4];
    const float* proj_w  = (const float*)d_in[5];
    const float* proj_b  = (const float*)d_in[6];
    const int*   relidx  = (const int*)d_in[7];
    float*       out     = (float*)d_out;

    static bool attrs_set = false;
    if (!attrs_set) {
        cudaFuncSetAttribute(qkv_gemm_kernel,
                             cudaFuncAttributeMaxDynamicSharedMemorySize,
                             GEMM_SMEM_BYTES);
        cudaFuncSetAttribute(proj_gemm_kernel,
                             cudaFuncAttributeMaxDynamicSharedMemorySize,
                             GEMM_SMEM_BYTES);
        cudaFuncSetAttribute(attn_mma_kernel,
                             cudaFuncAttributeMaxDynamicSharedMemorySize,
                             AT_SMEM_BYTES);
        attrs_set = true;
    }

    __half* xh_p;  cudaGetSymbolAddress((void**)&xh_p,  g_xh);
    __half* wh_p;  cudaGetSymbolAddress((void**)&wh_p,  g_wh);
    __half* pwh_p; cudaGetSymbolAddress((void**)&pwh_p, g_pwh);

    // 0. Convert GEMM operands to half
    {
        int n4 = (M_ROWS * CH) / 4;
        to_half_kernel<<<(n4 + 255) / 256, 256>>>(x, xh_p, n4);
        n4 = (THREE_C * CH) / 4;
        to_half_kernel<<<(n4 + 255) / 256, 256>>>(qkv_w, wh_p, n4);
        n4 = (CH * CH) / 4;
        to_half_kernel<<<(n4 + 255) / 256, 256>>>(proj_w, pwh_p, n4);
    }
    // 1. QKV projection
    {
        dim3 grid(THREE_C / BN, M_ROWS / BM);   // (18, 392)
        qkv_gemm_kernel<<<grid, 256, GEMM_SMEM_BYTES>>>(q_bias, v_bias);
    }
    // 2. RPB gather (half, padded)
    {
        const int total = NH * SEQ * RPB_LD;
        rpb_gather_kernel<<<(total + 255) / 256, 256>>>(rpb_tab, relidx);
    }
    // 3. Attention (single-pass, 448 threads)
    {
        attn_mma_kernel<<<BATCH * NH, NT_AT, AT_SMEM_BYTES>>>();
    }
    // 4. Projection
    {
        dim3 grid(CH / BN, M_ROWS / BM);        // (6, 392)
        proj_gemm_kernel<<<grid, 256, GEMM_SMEM_BYTES>>>(proj_b, out);
    }
}

// round 17
// speedup vs baseline: 1.1271x; 1.0381x over previous
#include <cuda_runtime.h>
#include <cuda_bf16.h>
#include <cuda_fp16.h>

// Problem constants
#define BATCH 256
#define SEQ   196
#define CH    768
#define NH    12
#define HD    64
#define M_ROWS (BATCH * SEQ)       // 50176
#define THREE_C (3 * CH)           // 2304
#define SCALE 0.125f
#define RPB_LD 208                 // padded rpb row length (halves)

// Scratch (q/k/v half, [B,H,N,hd])
__device__ __half g_q[(size_t)BATCH * NH * SEQ * HD];
__device__ __half g_k[(size_t)BATCH * NH * SEQ * HD];
__device__ __half g_v[(size_t)BATCH * NH * SEQ * HD];
__device__ __half g_rpbh[(size_t)NH * SEQ * RPB_LD];   // [H,196,208] half
__device__ __half g_att[(size_t)M_ROWS * CH];          // [B,N,C] half
__device__ __half g_xh[(size_t)M_ROWS * CH];
__device__ __half g_wh[(size_t)THREE_C * CH];
__device__ __half g_pwh[(size_t)CH * CH];

// ---------------------------------------------------------------------------
// PTX helpers
// ---------------------------------------------------------------------------
__device__ __forceinline__ void cp_async16(void* smem_ptr, const void* gmem_ptr) {
    unsigned saddr = (unsigned)__cvta_generic_to_shared(smem_ptr);
    asm volatile("cp.async.cg.shared.global [%0], [%1], 16;\n"
                 :: "r"(saddr), "l"(gmem_ptr));
}
__device__ __forceinline__ void cp_commit() {
    asm volatile("cp.async.commit_group;\n");
}
template <int N>
__device__ __forceinline__ void cp_wait() {
    asm volatile("cp.async.wait_group %0;\n" :: "n"(N));
}
__device__ __forceinline__ void mma_f16(float c[4], unsigned a0, unsigned a1,
                                        unsigned a2, unsigned a3,
                                        unsigned b0, unsigned b1) {
    asm volatile(
        "mma.sync.aligned.m16n8k16.row.col.f32.f16.f16.f32 "
        "{%0,%1,%2,%3}, {%4,%5,%6,%7}, {%8,%9}, {%0,%1,%2,%3};\n"
        : "+f"(c[0]), "+f"(c[1]), "+f"(c[2]), "+f"(c[3])
        : "r"(a0), "r"(a1), "r"(a2), "r"(a3), "r"(b0), "r"(b1));
}
__device__ __forceinline__ void ldm_x4(unsigned& r0, unsigned& r1,
                                       unsigned& r2, unsigned& r3, unsigned addr) {
    asm volatile("ldmatrix.sync.aligned.m8n8.x4.shared.b16 {%0,%1,%2,%3}, [%4];"
                 : "=r"(r0), "=r"(r1), "=r"(r2), "=r"(r3) : "r"(addr));
}
__device__ __forceinline__ void ldm_x4_t(unsigned& r0, unsigned& r1,
                                         unsigned& r2, unsigned& r3, unsigned addr) {
    asm volatile("ldmatrix.sync.aligned.m8n8.x4.trans.shared.b16 {%0,%1,%2,%3}, [%4];"
                 : "=r"(r0), "=r"(r1), "=r"(r2), "=r"(r3) : "r"(addr));
}

// ---------------------------------------------------------------------------
// Kernel 0: fused fp32 -> half conversion for x, qkv_w, proj_w (one launch)
// ---------------------------------------------------------------------------
#define N4_X  ((M_ROWS * CH) / 4)
#define N4_W  ((THREE_C * CH) / 4)
#define N4_PW ((CH * CH) / 4)

__global__ void to_half3_kernel(const float* __restrict__ sx,
                                const float* __restrict__ sw,
                                const float* __restrict__ spw)
{
    int i = blockIdx.x * blockDim.x + threadIdx.x;
    const float* src;
    __half* dst;
    if (i < N4_X)                 { src = sx;  dst = g_xh;  }
    else if (i < N4_X + N4_W)     { src = sw;  dst = g_wh;  i -= N4_X; }
    else if (i < N4_X + N4_W + N4_PW) { src = spw; dst = g_pwh; i -= N4_X + N4_W; }
    else return;
    float4 v = ((const float4*)src)[i];
    ((__half2*)dst)[i * 2 + 0] = __floats2half2_rn(v.x, v.y);
    ((__half2*)dst)[i * 2 + 1] = __floats2half2_rn(v.z, v.w);
}

// ---------------------------------------------------------------------------
// FP16 mma GEMM (frozen R13 config): BK=64, 3-stage, 128x128, 256 threads.
// ---------------------------------------------------------------------------
#define BM 128
#define BN 128
#define BK 64
#define NSTAGE 3
#define LDH 72
#define STAGE_HALVES ((BM + BN) * LDH)                  // 18432
#define STAGE_BYTES (STAGE_HALVES * 2)                  // 36864
#define GEMM_SMEM_BYTES (NSTAGE * STAGE_BYTES)          // 110592
#define CLD 136
#define CLDF 132                   // proj float bounce row stride

__device__ __forceinline__
void gemm_mainloop(const __half* __restrict__ Aptr,
                   const __half* __restrict__ Bptr,
                   __half* smh, int tid, float acc[4][4][4])
{
    const int warp = tid >> 5;
    const int lane = tid & 31;
    const int wr = warp & 1;
    const int wc = warp >> 1;
    const int grp = lane >> 3;
    const int lrow = lane & 7;

    #pragma unroll
    for (int i = 0; i < 4; i++)
        #pragma unroll
        for (int j = 0; j < 4; j++)
            #pragma unroll
            for (int t = 0; t < 4; t++) acc[i][j][t] = 0.f;

    const int ldr = tid >> 3;
    const int ldc = tid & 7;

    auto prefetch = [&](int stage, int k0) {
        __half* As = smh + stage * STAGE_HALVES;
        __half* Bs = As + BM * LDH;
        #pragma unroll
        for (int p = 0; p < 4; p++) {
            const int row = p * 32 + ldr;
            cp_async16(As + row * LDH + ldc * 8,
                       Aptr + (size_t)row * CH + k0 + ldc * 8);
            cp_async16(Bs + row * LDH + ldc * 8,
                       Bptr + (size_t)row * CH + k0 + ldc * 8);
        }
    };

    prefetch(0, 0);   cp_commit();
    prefetch(1, BK);  cp_commit();

    const unsigned smbase = (unsigned)__cvta_generic_to_shared(smh);
    const unsigned a_off = ((wr * 64 + (grp & 1) * 8 + lrow) * LDH
                            + (grp >> 1) * 8) * 2;
    const unsigned b_off = (unsigned)(BM * LDH * 2)
                         + ((wc * 32 + (grp >> 1) * 8 + lrow) * LDH
                            + (grp & 1) * 8) * 2;

    const int NKT = CH / BK;     // 12
    int sC = 0, sF = 2;

    #pragma unroll 1
    for (int kt = 0; kt < NKT; kt++) {
        cp_wait<1>();
        __syncthreads();

        if (kt + 2 < NKT) prefetch(sF, (kt + 2) * BK);
        cp_commit();

        const unsigned stage_addr = smbase + sC * STAGE_BYTES;
        const unsigned a_base = stage_addr + a_off;
        const unsigned b_base = stage_addr + b_off;

        #pragma unroll
        for (int s = 0; s < 4; s++) {
            unsigned a[4][4], b[4][2];
            #pragma unroll
            for (int mi = 0; mi < 4; mi++)
                ldm_x4(a[mi][0], a[mi][1], a[mi][2], a[mi][3],
                       a_base + (mi * 16 * LDH + s * 16) * 2);
            #pragma unroll
            for (int np = 0; np < 2; np++)
                ldm_x4(b[2 * np][0], b[2 * np][1], b[2 * np + 1][0], b[2 * np + 1][1],
                       b_base + (np * 16 * LDH + s * 16) * 2);
            #pragma unroll
            for (int mi = 0; mi < 4; mi++)
                #pragma unroll
                for (int ni = 0; ni < 4; ni++)
                    mma_f16(acc[mi][ni], a[mi][0], a[mi][1], a[mi][2], a[mi][3],
                            b[ni][0], b[ni][1]);
        }
        sC = (sC + 1 == NSTAGE) ? 0 : sC + 1;
        sF = (sF + 1 == NSTAGE) ? 0 : sF + 1;
    }
}

// ---------------------------------------------------------------------------
// Kernel 1: fused QKV projection (frozen R13)
// ---------------------------------------------------------------------------
__global__ __launch_bounds__(256, 2)
void qkv_gemm_kernel(const float* __restrict__ qb,
                     const float* __restrict__ vb)
{
    extern __shared__ __half smh[];
    const int bn = blockIdx.x;
    const int bm = blockIdx.y;
    const int tid = threadIdx.x;

    float acc[4][4][4];
    gemm_mainloop(g_xh + (size_t)(bm * BM) * CH, g_wh + (size_t)(bn * BN) * CH,
                  smh, tid, acc);

    const int warp = tid >> 5;
    const int lane = tid & 31;
    const int g = lane >> 2, tg = lane & 3;
    const int wr = warp & 1, wc = warp >> 1;

    const int jblock = bn * BN;
    const int which = jblock / CH;

    __syncthreads();

    #pragma unroll
    for (int mi = 0; mi < 4; mi++) {
        #pragma unroll
        for (int ni = 0; ni < 4; ni++) {
            const int jl = wc * 32 + ni * 8 + tg * 2;
            const int cbase = jblock + jl - which * CH;
            #pragma unroll
            for (int rr = 0; rr < 2; rr++) {
                const int row = wr * 64 + mi * 16 + g + rr * 8;
                const float v0 = acc[mi][ni][rr * 2 + 0];
                const float v1 = acc[mi][ni][rr * 2 + 1];
                __half2 h2;
                if (which == 0) {
                    float2 qb2 = *(const float2*)(qb + cbase);
                    h2 = __floats2half2_rn((v0 + qb2.x) * SCALE, (v1 + qb2.y) * SCALE);
                } else if (which == 1) {
                    h2 = __floats2half2_rn(v0, v1);
                } else {
                    float2 vb2 = *(const float2*)(vb + cbase);
                    h2 = __floats2half2_rn(v0 + vb2.x, v1 + vb2.y);
                }
                *(__half2*)(smh + row * CLD + jl) = h2;
            }
        }
    }
    __syncthreads();

    __half* dstT = (which == 0) ? g_q : (which == 1) ? g_k : g_v;
    #pragma unroll
    for (int it = 0; it < 8; it++) {
        const int idx = tid + it * 256;
        const int r = idx >> 4;
        const int cb = (idx & 15) * 8;
        const int cbase = jblock + cb - which * CH;
        const int h = cbase >> 6;
        const int d = cbase & 63;
        const int m = bm * BM + r;
        const int b = m / SEQ;
        const int n = m - b * SEQ;
        const uint4 val = *(const uint4*)(smh + r * CLD + cb);
        *(uint4*)(dstT + (((size_t)(b * NH + h)) * SEQ + n) * HD + d) = val;
    }
}

// ---------------------------------------------------------------------------
// Kernel 2: rpb gather -> half, padded [H][196][208]
// ---------------------------------------------------------------------------
__global__ void rpb_gather_kernel(const float* __restrict__ table,
                                  const int* __restrict__ relidx)
{
    int idx = blockIdx.x * blockDim.x + threadIdx.x;
    const int total = NH * SEQ * RPB_LD;
    if (idx >= total) return;
    const int h = idx / (SEQ * RPB_LD);
    const int rem = idx - h * SEQ * RPB_LD;
    const int i = rem / RPB_LD;
    const int j = rem - i * RPB_LD;
    __half v = __float2half(0.f);
    if (j < SEQ) v = __float2half(table[relidx[i * SEQ + j] * NH + h]);
    g_rpbh[idx] = v;
}

// ---------------------------------------------------------------------------
// Kernel 3: FP16 mma attention, single-pass, 448 threads, trans-ldmatrix V.
// Qs [208][72], Ks [208][72], Vs [208][72] row-major, P [208][216].
// ---------------------------------------------------------------------------
#define NT_AT 448
#define LQ 72
#define LP 216
#define KROWS 208
#define AQ_OFF 0
#define AK_OFF (KROWS * LQ)               // 14976
#define AV_OFF (AK_OFF + KROWS * LQ)      // 29952
#define AP_OFF (AV_OFF + KROWS * LQ)      // 44928
#define AT_SMEM_HALVES (AP_OFF + KROWS * LP)   // 89856
#define AT_SMEM_BYTES (AT_SMEM_HALVES * 2)     // 179712

__global__ __launch_bounds__(NT_AT, 1)
void attn_mma_kernel()
{
    extern __shared__ __half smh[];
    __half* Qs = smh + AQ_OFF;       // [208][72]
    __half* Ks = smh + AK_OFF;       // [208][72]
    __half* Vs = smh + AV_OFF;       // [208][72] row-major (key, d)
    __half* P  = smh + AP_OFF;       // [208][216]

    const int bh = blockIdx.x;
    const int b = bh / NH;
    const int h = bh % NH;
    const int tid = threadIdx.x;
    const int warp = tid >> 5;
    const int lane = tid & 31;
    const int g = lane >> 2;
    const int tg = lane & 3;
    const int grp = lane >> 3;
    const int lrow = lane & 7;

    const __half* Qg = g_q + (size_t)bh * SEQ * HD;
    const __half* Kg = g_k + (size_t)bh * SEQ * HD;
    const __half* Vg = g_v + (size_t)bh * SEQ * HD;
    const __half* rpbh = g_rpbh + (size_t)h * SEQ * RPB_LD;

    const uint4 z16 = make_uint4(0, 0, 0, 0);

    // stage Q, K, V [208 rows x 8 chunks each] (zero rows 196..207)
    for (int t = tid; t < KROWS * 8; t += NT_AT) {
        const int r = t >> 3, c = (t & 7) * 8;
        if (r < SEQ) {
            cp_async16(Qs + r * LQ + c, Qg + r * HD + c);
            cp_async16(Ks + r * LQ + c, Kg + r * HD + c);
            cp_async16(Vs + r * LQ + c, Vg + r * HD + c);
        } else {
            *(uint4*)(Qs + r * LQ + c) = z16;
            *(uint4*)(Ks + r * LQ + c) = z16;
            *(uint4*)(Vs + r * LQ + c) = z16;
        }
    }
    cp_commit();
    cp_wait<0>();
    __syncthreads();

    if (warp >= 13) return;   // warps 0..12 compute rows 0..207

    __half* attbase = g_att + (size_t)b * SEQ * CH + h * HD;

    const unsigned smb = (unsigned)__cvta_generic_to_shared(smh);
    const int r0 = warp * 16;
    const unsigned q_base = smb + (unsigned)(AQ_OFF * 2)
                          + ((r0 + (grp & 1) * 8 + lrow) * LQ + (grp >> 1) * 8) * 2;
    const unsigned k_base = smb + (unsigned)(AK_OFF * 2)
                          + (((grp >> 1) * 8 + lrow) * LQ + (grp & 1) * 8) * 2;
    const unsigned p_base = smb + (unsigned)(AP_OFF * 2)
                          + ((r0 + (grp & 1) * 8 + lrow) * LP + (grp >> 1) * 8) * 2;
    // trans V: rows = key, cols = d. grp -> (k-half, n-half-of-16)
    const unsigned v_base = smb + (unsigned)(AV_OFF * 2)
                          + (((grp & 1) * 8 + lrow) * LQ + (grp >> 1) * 8) * 2;

    // ---- Phase 1: S = Q @ K^T (26 n-tiles over 208 keys) ----
    float acc[26][4];
    #pragma unroll
    for (int t = 0; t < 26; t++)
        #pragma unroll
        for (int e = 0; e < 4; e++) acc[t][e] = 0.f;

    #pragma unroll
    for (int ks = 0; ks < 4; ks++) {
        const int k0 = ks * 16;
        unsigned a0, a1, a2, a3;
        ldm_x4(a0, a1, a2, a3, q_base + k0 * 2);
        #pragma unroll
        for (int tp = 0; tp < 13; tp++) {
            unsigned b0, b1, b2, b3;
            ldm_x4(b0, b1, b2, b3, k_base + (tp * 16 * LQ + k0) * 2);
            mma_f16(acc[2 * tp + 0], a0, a1, a2, a3, b0, b1);
            mma_f16(acc[2 * tp + 1], a0, a1, a2, a3, b2, b3);
        }
    }

    // ---- rpb add (direct ldg, half2) + masking ----
    const int rlo = r0 + g;
    const int rhi = rlo + 8;
    const __half* rp_lo = rpbh + (size_t)min(rlo, SEQ - 1) * RPB_LD;
    const __half* rp_hi = rpbh + (size_t)min(rhi, SEQ - 1) * RPB_LD;
    #pragma unroll
    for (int t = 0; t < 26; t++) {
        const int c0 = t * 8 + 2 * tg;
        const float2 flo = __half22float2(__ldg((const __half2*)(rp_lo + c0)));
        const float2 fhi = __half22float2(__ldg((const __half2*)(rp_hi + c0)));
        if (c0 < SEQ)     { acc[t][0] += flo.x; acc[t][2] += fhi.x; }
        else              { acc[t][0] = -1e30f; acc[t][2] = -1e30f; }
        if (c0 + 1 < SEQ) { acc[t][1] += flo.y; acc[t][3] += fhi.y; }
        else              { acc[t][1] = -1e30f; acc[t][3] = -1e30f; }
    }

    // ---- softmax ----
    float mlo = -1e30f, mhi = -1e30f;
    #pragma unroll
    for (int t = 0; t < 26; t++) {
        mlo = fmaxf(mlo, fmaxf(acc[t][0], acc[t][1]));
        mhi = fmaxf(mhi, fmaxf(acc[t][2], acc[t][3]));
    }
    mlo = fmaxf(mlo, __shfl_xor_sync(0xffffffffu, mlo, 1));
    mlo = fmaxf(mlo, __shfl_xor_sync(0xffffffffu, mlo, 2));
    mhi = fmaxf(mhi, __shfl_xor_sync(0xffffffffu, mhi, 1));
    mhi = fmaxf(mhi, __shfl_xor_sync(0xffffffffu, mhi, 2));

    float llo = 0.f, lhi = 0.f;
    __half* Prow_lo = P + (r0 + g) * LP;
    __half* Prow_hi = P + (r0 + g + 8) * LP;
    #pragma unroll
    for (int t = 0; t < 26; t++) {
        const int c0 = t * 8 + 2 * tg;
        const __half2 p01 = __floats2half2_rn(__expf(acc[t][0] - mlo),
                                              __expf(acc[t][1] - mlo));
        const __half2 p23 = __floats2half2_rn(__expf(acc[t][2] - mhi),
                                              __expf(acc[t][3] - mhi));
        const float2 f01 = __half22float2(p01);
        const float2 f23 = __half22float2(p23);
        llo += f01.x + f01.y;
        lhi += f23.x + f23.y;
        *(__half2*)(Prow_lo + c0) = p01;
        *(__half2*)(Prow_hi + c0) = p23;
    }

    llo += __shfl_xor_sync(0xffffffffu, llo, 1);
    llo += __shfl_xor_sync(0xffffffffu, llo, 2);
    lhi += __shfl_xor_sync(0xffffffffu, lhi, 1);
    lhi += __shfl_xor_sync(0xffffffffu, lhi, 2);
    const float inv_lo = 1.f / llo;
    const float inv_hi = 1.f / lhi;

    __syncwarp();   // own P rows complete (only own rows read back)

    // ---- Phase 2: O = P @ V (13 k16 steps; trans ldmatrix on row-major V) ----
    float oacc[8][4];
    #pragma unroll
    for (int nt = 0; nt < 8; nt++)
        #pragma unroll
        for (int e = 0; e < 4; e++) oacc[nt][e] = 0.f;

    #pragma unroll
    for (int kt = 0; kt < 13; kt++) {
        const int k0 = kt * 16;
        unsigned a0, a1, a2, a3;
        ldm_x4(a0, a1, a2, a3, p_base + k0 * 2);
        #pragma unroll
        for (int ntp = 0; ntp < 4; ntp++) {
            unsigned b0, b1, b2, b3;
            ldm_x4_t(b0, b1, b2, b3, v_base + (kt * 16 * LQ + ntp * 16) * 2);
            mma_f16(oacc[2 * ntp + 0], a0, a1, a2, a3, b0, b1);
            mma_f16(oacc[2 * ntp + 1], a0, a1, a2, a3, b2, b3);
        }
    }

    // ---- store O as half ----
    #pragma unroll
    for (int nt = 0; nt < 8; nt++) {
        const int c = nt * 8 + 2 * tg;
        if (rlo < SEQ)
            *(__half2*)(attbase + (size_t)rlo * CH + c) =
                __floats2half2_rn(oacc[nt][0] * inv_lo, oacc[nt][1] * inv_lo);
        if (rhi < SEQ)
            *(__half2*)(attbase + (size_t)rhi * CH + c) =
                __floats2half2_rn(oacc[nt][2] * inv_hi, oacc[nt][3] * inv_hi);
    }
}

// ---------------------------------------------------------------------------
// Kernel 4: output projection (smem-bounced coalesced fp32 stores)
// ---------------------------------------------------------------------------
__global__ __launch_bounds__(256, 2)
void proj_gemm_kernel(const float* __restrict__ pb,
                      float* __restrict__ out)
{
    extern __shared__ __half smh[];
    float* smf = (float*)smh;   // [128][CLDF] fp32 bounce
    const int bn = blockIdx.x;
    const int bm = blockIdx.y;
    const int tid = threadIdx.x;

    float acc[4][4][4];
    gemm_mainloop(g_att + (size_t)(bm * BM) * CH, g_pwh + (size_t)(bn * BN) * CH,
                  smh, tid, acc);

    const int warp = tid >> 5;
    const int lane = tid & 31;
    const int g = lane >> 2, tg = lane & 3;
    const int wr = warp & 1, wc = warp >> 1;

    __syncthreads();   // ldmatrix reads done before overwriting stage smem

    #pragma unroll
    for (int mi = 0; mi < 4; mi++) {
        #pragma unroll
        for (int ni = 0; ni < 4; ni++) {
            const int jl = wc * 32 + ni * 8 + tg * 2;
            const float2 pb2 = *(const float2*)(pb + bn * BN + jl);
            #pragma unroll
            for (int rr = 0; rr < 2; rr++) {
                const int row = wr * 64 + mi * 16 + g + rr * 8;
                float2 o2;
                o2.x = acc[mi][ni][rr * 2 + 0] + pb2.x;
                o2.y = acc[mi][ni][rr * 2 + 1] + pb2.y;
                *(float2*)(smf + row * CLDF + jl) = o2;
            }
        }
    }
    __syncthreads();

    // coalesced write-out: 16B chunks (128 rows x 32 chunks = 4096)
    #pragma unroll
    for (int it = 0; it < 16; it++) {
        const int idx = tid + it * 256;         // 0..4095
        const int r = idx >> 5;                 // row 0..127
        const int cb = (idx & 31) * 4;          // col base (floats)
        const int i = bm * BM + r;
        const uint4 val = *(const uint4*)(smf + r * CLDF + cb);
        *(uint4*)(out + (size_t)i * CH + bn * BN + cb) = val;
    }
}

// ---------------------------------------------------------------------------
// Launch
// ---------------------------------------------------------------------------
extern "C" void kernel_launch(void* const* d_in, const int* in_sizes, int n_in,
                              void* d_out, int out_size)
{
    const float* x       = (const float*)d_in[0];
    const float* qkv_w   = (const float*)d_in[1];
    const float* q_bias  = (const float*)d_in[2];
    const float* v_bias  = (const float*)d_in[3];
    const float* rpb_tab = (const float*)d_in[4];
    const float* proj_w  = (const float*)d_in[5];
    const float* proj_b  = (const float*)d_in[6];
    const int*   relidx  = (const int*)d_in[7];
    float*       out     = (float*)d_out;

    static bool attrs_set = false;
    if (!attrs_set) {
        cudaFuncSetAttribute(qkv_gemm_kernel,
                             cudaFuncAttributeMaxDynamicSharedMemorySize,
                             GEMM_SMEM_BYTES);
        cudaFuncSetAttribute(proj_gemm_kernel,
                             cudaFuncAttributeMaxDynamicSharedMemorySize,
                             GEMM_SMEM_BYTES);
        cudaFuncSetAttribute(attn_mma_kernel,
                             cudaFuncAttributeMaxDynamicSharedMemorySize,
                             AT_SMEM_BYTES);
        attrs_set = true;
    }

    // 0. Convert GEMM operands to half (single launch)
    {
        const int total = N4_X + N4_W + N4_PW;
        to_half3_kernel<<<(total + 255) / 256, 256>>>(x, qkv_w, proj_w);
    }
    // 1. QKV projection
    {
        dim3 grid(THREE_C / BN, M_ROWS / BM);   // (18, 392)
        qkv_gemm_kernel<<<grid, 256, GEMM_SMEM_BYTES>>>(q_bias, v_bias);
    }
    // 2. RPB gather (half, padded)
    {
        const int total = NH * SEQ * RPB_LD;
        rpb_gather_kernel<<<(total + 255) / 256, 256>>>(rpb_tab, relidx);
    }
    // 3. Attention (single-pass, trans-ldmatrix V)
    {
        attn_mma_kernel<<<BATCH * NH, NT_AT, AT_SMEM_BYTES>>>();
    }
    // 4. Projection
    {
        dim3 grid(CH / BN, M_ROWS / BM);        // (6, 392)
        proj_gemm_kernel<<<grid, 256, GEMM_SMEM_BYTES>>>(proj_b, out);
    }
}